// round 14
// baseline (speedup 1.0000x reference)
#include <cuda_runtime.h>
#include <cuda_bf16.h>

#define HH 320
#define WW 320
#define KS 31
#define PADK 15
#define HOUT 289        // 320 - 16 - 15
#define NCOMBO 3600     // 180 thetas x 20 freqs
#define KROW 32         // padded kernel row (31 + 1 zero)
#define KSTRIDE (KS * KROW)   // 992 floats per combo = 31 x 128B lines

#define PXB 16          // pixels per conv tile (two per warp) — measured-best
#define NWARP 8
#define SMR KS          // smem rows 31
#define SMC 48          // smem cols (46 used, padded)
#define GX 19           // ceil(289/16)
#define NBORDER 18879   // 320^2 - 289^2
#define NTILE (GX * (HOUT + 4))       // conv rows + 4 border-sweep rows = 5567
#define NFILL (180 * 31 * 8 * 2)      // fill units: theta x row x quad x fsplit
#define NTHR4 ((HH * WW) / 4)         // threshold float4 units = 25600

// Precomputed Gabor kernel table: [3600][31*32] floats = 14.27 MB (L2-resident).
__device__ __align__(16) float g_ker[NCOMBO * KSTRIDE];
// Scratch for global min/max (monotonic-uint encoded floats).
__device__ unsigned g_mm[2];
// Grid barrier state (zero-init; returns to zero every launch: phase 0->1->0).
__device__ unsigned g_cnt;
__device__ unsigned g_phase;

__device__ __forceinline__ unsigned encf(float f) {
    unsigned u = __float_as_uint(f);
    return (u & 0x80000000u) ? ~u : (u | 0x80000000u);
}
__device__ __forceinline__ float decf(unsigned u) {
    return (u & 0x80000000u) ? __uint_as_float(u ^ 0x80000000u)
                             : __uint_as_float(~u);
}
__device__ __forceinline__ unsigned ldacq(const unsigned* p) {
    unsigned v;
    asm volatile("ld.acquire.gpu.global.u32 %0, [%1];" : "=r"(v) : "l"(p));
    return v;
}

// Sense-reversing grid barrier. All blocks co-resident by construction
// (grid = numSM * occupancy), so the spin cannot deadlock.
__device__ __forceinline__ void gbar(int nblk, unsigned target) {
    __threadfence();                 // publish this thread's global writes
    __syncthreads();
    if (threadIdx.x == 0) {
        const unsigned prev = atomicAdd(&g_cnt, 1u);
        if (prev == (unsigned)nblk - 1u) {
            g_cnt = 0u;              // safe: all others already arrived (spinning)
            __threadfence();
            atomicExch(&g_phase, target);
        } else {
            while (ldacq(&g_phase) != target) __nanosleep(40);
        }
    }
    __syncthreads();
}

// One persistent kernel: Phase F (fill table) -> barrier -> Phase C (conv +
// border min/max over tiles) -> barrier -> Phase T (normalize + threshold).
// All FP expressions bitwise-identical to the validated multi-kernel version.
__global__ __launch_bounds__(256) void k_all(
    const float* __restrict__ fp,
    const int*   __restrict__ fmap,
    const int*   __restrict__ tmap,
    float* __restrict__ out,
    int nblk)
{
    __shared__ float sm[SMR * SMC];
    __shared__ unsigned swmin[NWARP], swmax[NWARP];

    const int tid  = threadIdx.x;
    const int lane = tid & 31;
    const int w    = tid >> 5;
    const int b    = blockIdx.x;

    // ---------------- Phase F: fill kernel table ----------------
    if (b == 0 && tid == 0) {
        g_mm[0] = 0xFFFFFFFFu;  // min identity (encoded)
        g_mm[1] = 0u;           // max identity
    }
    for (int u = b * 256 + tid; u < NFILL; u += nblk * 256) {
        const int t   = u / 496;          // theta 0..179
        const int rem = u % 496;
        const int row = rem >> 4;         // 0..30
        const int quad = (rem >> 1) & 7;  // 0..7
        const int f0i = (rem & 1) * 10;   // freq split

        const float th = (float)t / 180.0f * 3.14159265358979323846f;
        float st, ct;
        sincosf(th, &st, &ct);            // precise — matches validated kernel

        const int qcol = quad * 4;
        const float y = (float)(row - PADK);
        const float yst = y * st;
        const float yct = y * ct;

        float env[4], c0[4], c1[4], k2[4];
        #pragma unroll
        for (int j = 0; j < 4; ++j) {
            const int bb = qcol + j;                 // col 0..31 (31 = pad)
            const float x  = (float)(bb - PADK);
            const float xt = fmaf(x, ct, yst);
            const float yt = fmaf(-x, st, yct);
            const float ga = fmaf(0.04f, fabsf(yt), 1.0f);
            const float gy = ga * yt;
            const float q  = fmaf(gy, gy, xt * xt);
            env[j] = (bb < KS) ? __expf(q * (-1.0f / 72.0f)) : 0.0f;
            const float C  = xt * fmaf(yt, 1.0f / 45.0f, 1.0f);  // xt*(1+yt/45)
            const float d  = (6.283185307179586f * 0.0015f) * C;
            const float a0 = fmaf((float)f0i, d, (6.283185307179586f * 0.025f) * C);
            c1[j] = __cosf(a0);          // T(0)  at fi = f0i
            c0[j] = __cosf(a0 - d);      // T(-1)
            k2[j] = 2.0f * __cosf(d);
        }

        float* dst = &g_ker[(t * 20 + f0i) * KSTRIDE + row * KROW + qcol];
        #pragma unroll
        for (int fi = 0; fi < 10; ++fi) {
            float4 wv;
            wv.x = env[0] * c1[0];
            wv.y = env[1] * c1[1];
            wv.z = env[2] * c1[2];
            wv.w = env[3] * c1[3];
            *reinterpret_cast<float4*>(dst + fi * KSTRIDE) = wv;
            #pragma unroll
            for (int j = 0; j < 4; ++j) {
                const float tn = fmaf(k2[j], c1[j], -c0[j]);
                c0[j] = c1[j]; c1[j] = tn;
            }
        }
    }

    gbar(nblk, 1u);   // table + g_mm init visible grid-wide

    // ---------------- Phase C: conv + border min/max ----------------
    for (int tile = b; tile < NTILE; tile += nblk) {
        const int bx = tile % GX;
        const int by = tile / GX;

        if (by < HOUT) {
            const int oy  = by;
            const int ox0 = bx * PXB;

            const int p0 = 2 * w, p1 = 2 * w + 1;
            const int ox0p = ox0 + p0, ox1p = ox0 + p1;
            const bool v0 = (ox0p < HOUT), v1 = (ox1p < HOUT);
            const int ci0 = (oy + PADK) * WW + (ox0p + PADK);
            const int ci1 = (oy + PADK) * WW + (ox1p + PADK);
            const int cis0 = v0 ? ci0 : (PADK * WW + PADK);
            const int cis1 = v1 ? ci1 : (PADK * WW + PADK);
            const int cb0 = tmap[cis0] * 20 + fmap[cis0];
            const int cb1 = tmap[cis1] * 20 + fmap[cis1];

            // Load patch rows oy..oy+30, cols ox0..ox0+47 (zero-fill OOB cols).
            for (int i = tid; i < SMR * SMC; i += 256) {
                const int r = i / SMC, c = i % SMC;
                const int gx = ox0 + c;
                sm[i] = (gx < WW) ? fp[(oy + r) * WW + gx] : 0.0f;
            }
            __syncthreads();

            const float* __restrict__ kr0 = &g_ker[cb0 * KSTRIDE];
            const float* __restrict__ kr1 = &g_ker[cb1 * KSTRIDE];

            float acc0 = 0.0f, acc1 = 0.0f;
            const float* __restrict__ pr0 = &sm[p0 + lane];
            #pragma unroll
            for (int a = 0; a < KS; ++a) {
                const float wv0 = kr0[a * KROW + lane];  // coalesced 128B line
                const float wv1 = kr1[a * KROW + lane];
                const float pv0 = pr0[a * SMC];          // conflict-free LDS
                const float pv1 = pr0[a * SMC + 1];
                acc0 = fmaf(pv0, wv0, acc0);
                acc1 = fmaf(pv1, wv1, acc1);
            }
            #pragma unroll
            for (int off = 16; off > 0; off >>= 1) {
                acc0 += __shfl_down_sync(0xFFFFFFFFu, acc0, off);
                acc1 += __shfl_down_sync(0xFFFFFFFFu, acc1, off);
            }

            if (lane == 0) {
                if (v0) out[ci0] = acc0;
                if (v1) out[ci1] = acc1;
                unsigned m0 = v0 ? encf(acc0) : 0xFFFFFFFFu;
                unsigned M0 = v0 ? encf(acc0) : 0u;
                unsigned m1 = v1 ? encf(acc1) : 0xFFFFFFFFu;
                unsigned M1 = v1 ? encf(acc1) : 0u;
                swmin[w] = min(m0, m1);
                swmax[w] = max(M0, M1);
            }
            __syncthreads();
            if (tid == 0) {
                unsigned m = 0xFFFFFFFFu, M = 0u;
                #pragma unroll
                for (int i = 0; i < NWARP; ++i) { m = min(m, swmin[i]); M = max(M, swmax[i]); }
                atomicMin(&g_mm[0], m);
                atomicMax(&g_mm[1], M);
            }
            __syncthreads();   // protect sm/swmin reuse across tile iterations
        } else {
            // Border min/max: 4 sweep rows x GX x 256 = 19456 >= 18879.
            const int k = ((by - HOUT) * GX + bx) * 256 + tid;
            unsigned km = 0xFFFFFFFFu, kM = 0u;
            if (k < NBORDER) {
                int row, col;
                if (k < 31 * WW) {                // full rows 0..14, 304..319
                    const int r = k / WW;
                    row = (r < PADK) ? r : r + HOUT;
                    col = k % WW;
                } else {                          // side cols of interior rows
                    const int k2 = k - 31 * WW;
                    row = PADK + k2 / 31;
                    const int c = k2 % 31;
                    col = (c < PADK) ? c : c + HOUT;
                }
                const float v = fp[row * WW + col];
                km = kM = encf(v);
            }
            km = __reduce_min_sync(0xFFFFFFFFu, km);
            kM = __reduce_max_sync(0xFFFFFFFFu, kM);
            if (lane == 0) { swmin[w] = km; swmax[w] = kM; }
            __syncthreads();
            if (tid == 0) {
                unsigned m = 0xFFFFFFFFu, M = 0u;
                #pragma unroll
                for (int i = 0; i < NWARP; ++i) { m = min(m, swmin[i]); M = max(M, swmax[i]); }
                atomicMin(&g_mm[0], m);
                atomicMax(&g_mm[1], M);
            }
            __syncthreads();
        }
    }

    gbar(nblk, 0u);   // out + g_mm final; phase returns to 0 for next replay

    // ---------------- Phase T: normalize + threshold ----------------
    const float mn  = decf(g_mm[0]);
    const float mxv = decf(g_mm[1]) - mn;      // max of (out - min)
    const float s   = (mxv != 0.0f) ? (100.0f / mxv) : 1.0f;

    for (int idx4 = b * 256 + tid; idx4 < NTHR4; idx4 += nblk * 256) {
        const int base = idx4 * 4;
        const int i = base / WW;
        const int j0 = base % WW;
        const bool rowin = (i >= PADK) && (i < PADK + HOUT);

        float4 ov = ((const float4*)out)[idx4];
        float4 fv = ((const float4*)fp)[idx4];
        float r[4] = {ov.x, ov.y, ov.z, ov.w};
        float f[4] = {fv.x, fv.y, fv.z, fv.w};
        #pragma unroll
        for (int c = 0; c < 4; ++c) {
            const int j = j0 + c;
            const bool inter = rowin && (j >= PADK) && (j < PADK + HOUT);
            const float src = inter ? r[c] : f[c];
            const float t = (src - mn) * s;
            r[c] = (t > 55.0f) ? 100.0f : 0.0f;
        }
        ((float4*)out)[idx4] = make_float4(r[0], r[1], r[2], r[3]);
    }
}

extern "C" void kernel_launch(void* const* d_in, const int* in_sizes, int n_in,
                              void* d_out, int out_size)
{
    const float* fp   = (const float*)d_in[0];   // fprint
    const int*   fmap = (const int*)d_in[1];     // freq_map
    const int*   tmap = (const int*)d_in[2];     // theta_map
    float* out = (float*)d_out;

    int numSM = 0, occ = 0;
    cudaDeviceGetAttribute(&numSM, cudaDevAttrMultiProcessorCount, 0);
    cudaOccupancyMaxActiveBlocksPerMultiprocessor(&occ, k_all, 256, 0);
    if (occ < 1) occ = 1;
    if (occ > 4) occ = 4;          // conservative co-residency guarantee
    const int nblk = numSM * occ;

    k_all<<<nblk, 256>>>(fp, fmap, tmap, out, nblk);
}

// round 15
// speedup vs baseline: 1.3918x; 1.3918x over previous
#include <cuda_runtime.h>
#include <cuda_bf16.h>

#define HH 320
#define WW 320
#define KS 31
#define PADK 15
#define HOUT 289        // 320 - 16 - 15
#define NCOMBO 3600     // 180 thetas x 20 freqs
#define KROW 32         // padded kernel row (31 + 1 zero)
#define KSTRIDE (KS * KROW)   // 992 floats per combo = 31 x 128B lines

#define PXB 16          // pixels per block (two per warp) — measured-best
#define NWARP 8
#define SMR KS          // smem rows 31
#define SMC 48          // smem cols (46 used, padded)
#define GX 19           // ceil(289/16)
#define NBORDER 18879   // 320^2 - 289^2

// Precomputed Gabor kernel table: [3600][31*32] floats = 14.27 MB (L2-resident).
__device__ __align__(16) float g_ker[NCOMBO * KSTRIDE];
// Scratch for global min/max (monotonic-uint encoded floats).
__device__ unsigned g_mm[2];

__device__ __forceinline__ unsigned encf(float f) {
    unsigned u = __float_as_uint(f);
    return (u & 0x80000000u) ? ~u : (u | 0x80000000u);
}
__device__ __forceinline__ float decf(unsigned u) {
    return (u & 0x80000000u) ? __uint_as_float(u ^ 0x80000000u)
                             : __uint_as_float(~u);
}

// Fill the kernel table. cos argument is linear in freq index:
//   arg(fi) = 2*pi*xt*(1+yt/45)*(0.025+0.0015*fi) = a0 + fi*d
// -> Chebyshev recurrence T(f+1)=2cos(d)*T(f)-T(f-1), reseeded at fi=10.
// Thread owns a 4-tap quad for 10 freqs; float4 stores.
// grid = (180, 2, 2): t = bx, rows [by*16, ...), freqs [bz*10, bz*10+10).
__global__ __launch_bounds__(128) void k_fill()
{
    __shared__ float s_st, s_ct;
    if (threadIdx.x == 0) {
        if (blockIdx.x == 0 && blockIdx.y == 0 && blockIdx.z == 0) {
            g_mm[0] = 0xFFFFFFFFu;  // min identity (encoded)
            g_mm[1] = 0u;           // max identity
        }
        const float th = (float)blockIdx.x / 180.0f * 3.14159265358979323846f;
        float st, ct;
        sincosf(th, &st, &ct);      // precise — same values as validated kernel
        s_st = st; s_ct = ct;
    }
    __syncthreads();

    const int t    = blockIdx.x;
    const int qi   = threadIdx.x;
    const int row  = blockIdx.y * 16 + (qi >> 3);   // 8 quads per row
    const int f0i  = blockIdx.z * 10;

    if (row < KS) {
        const float st = s_st, ct = s_ct;
        const int qcol = (qi & 7) * 4;
        const float y = (float)(row - PADK);
        const float yst = y * st;
        const float yct = y * ct;

        float env[4], c0[4], c1[4], k2[4];
        #pragma unroll
        for (int j = 0; j < 4; ++j) {
            const int b = qcol + j;                  // col 0..31 (31 = pad)
            const float x  = (float)(b - PADK);
            const float xt = fmaf(x, ct, yst);
            const float yt = fmaf(-x, st, yct);
            const float ga = fmaf(0.04f, fabsf(yt), 1.0f);
            const float gy = ga * yt;
            const float q  = fmaf(gy, gy, xt * xt);
            env[j] = (b < KS) ? __expf(q * (-1.0f / 72.0f)) : 0.0f;
            const float C  = xt * fmaf(yt, 1.0f / 45.0f, 1.0f);  // xt*(1+yt/45)
            const float d  = (6.283185307179586f * 0.0015f) * C;
            const float a0 = fmaf((float)f0i, d, (6.283185307179586f * 0.025f) * C);
            c1[j] = __cosf(a0);          // T(0)  at fi = f0i
            c0[j] = __cosf(a0 - d);      // T(-1)
            k2[j] = 2.0f * __cosf(d);
        }

        float* dst = &g_ker[(t * 20 + f0i) * KSTRIDE + row * KROW + qcol];
        #pragma unroll
        for (int fi = 0; fi < 10; ++fi) {
            float4 wv;
            wv.x = env[0] * c1[0];
            wv.y = env[1] * c1[1];
            wv.z = env[2] * c1[2];
            wv.w = env[3] * c1[3];
            *reinterpret_cast<float4*>(dst + fi * KSTRIDE) = wv;
            #pragma unroll
            for (int j = 0; j < 4; ++j) {
                const float tn = fmaf(k2[j], c1[j], -c0[j]);
                c0[j] = c1[j]; c1[j] = tn;
            }
        }
    }
#if __CUDA_ARCH__ >= 900
    cudaTriggerProgrammaticLaunchCompletion();
#endif
}

// Convolution + border min/max. gridDim = (GX, HOUT + 4), block = 256.
// PDL: everything up to the gridDependencySynchronize reads only harness
// inputs (fp/fmap/tmap) and may overlap k_fill's tail.
__global__ __launch_bounds__(256) void k_conv(
    const float* __restrict__ fp,
    const int*   __restrict__ fmap,
    const int*   __restrict__ tmap,
    float* __restrict__ out)
{
    __shared__ float sm[SMR * SMC];
    __shared__ unsigned swmin[NWARP], swmax[NWARP];

    const int tid  = threadIdx.x;
    const int lane = tid & 31;
    const int w    = tid >> 5;
    const int by   = blockIdx.y;

    if (by < HOUT) {
        const int oy  = by;
        const int ox0 = blockIdx.x * PXB;

        // Combo indices (input reads) before smem fill — overlaps L2 latency.
        const int p0 = 2 * w, p1 = 2 * w + 1;
        const int ox0p = ox0 + p0, ox1p = ox0 + p1;
        const bool v0 = (ox0p < HOUT), v1 = (ox1p < HOUT);
        const int ci0 = (oy + PADK) * WW + (ox0p + PADK);
        const int ci1 = (oy + PADK) * WW + (ox1p + PADK);
        const int cis0 = v0 ? ci0 : (PADK * WW + PADK);
        const int cis1 = v1 ? ci1 : (PADK * WW + PADK);
        const int cb0 = tmap[cis0] * 20 + fmap[cis0];
        const int cb1 = tmap[cis1] * 20 + fmap[cis1];

        // Load patch rows oy..oy+30, cols ox0..ox0+47 (zero-fill OOB cols).
        for (int i = tid; i < SMR * SMC; i += 256) {
            const int r = i / SMC, c = i % SMC;
            const int gx = ox0 + c;
            sm[i] = (gx < WW) ? fp[(oy + r) * WW + gx] : 0.0f;
        }
        __syncthreads();

#if __CUDA_ARCH__ >= 900
        cudaGridDependencySynchronize();   // wait for k_fill's g_ker/g_mm
#endif
        const float* __restrict__ kr0 = &g_ker[cb0 * KSTRIDE];
        const float* __restrict__ kr1 = &g_ker[cb1 * KSTRIDE];

        float acc0 = 0.0f, acc1 = 0.0f;
        const float* __restrict__ pr0 = &sm[p0 + lane];
        #pragma unroll
        for (int a = 0; a < KS; ++a) {
            const float wv0 = kr0[a * KROW + lane];  // one coalesced 128B line
            const float wv1 = kr1[a * KROW + lane];
            const float pv0 = pr0[a * SMC];          // conflict-free LDS
            const float pv1 = pr0[a * SMC + 1];
            acc0 = fmaf(pv0, wv0, acc0);
            acc1 = fmaf(pv1, wv1, acc1);
        }
        #pragma unroll
        for (int off = 16; off > 0; off >>= 1) {
            acc0 += __shfl_down_sync(0xFFFFFFFFu, acc0, off);
            acc1 += __shfl_down_sync(0xFFFFFFFFu, acc1, off);
        }

        if (lane == 0) {
            if (v0) out[ci0] = acc0;
            if (v1) out[ci1] = acc1;
            unsigned m0 = v0 ? encf(acc0) : 0xFFFFFFFFu;
            unsigned M0 = v0 ? encf(acc0) : 0u;
            unsigned m1 = v1 ? encf(acc1) : 0xFFFFFFFFu;
            unsigned M1 = v1 ? encf(acc1) : 0u;
            swmin[w] = min(m0, m1);
            swmax[w] = max(M0, M1);
        }
        __syncthreads();
        if (tid == 0) {
            unsigned m = 0xFFFFFFFFu, M = 0u;
            #pragma unroll
            for (int i = 0; i < NWARP; ++i) { m = min(m, swmin[i]); M = max(M, swmax[i]); }
            atomicMin(&g_mm[0], m);
            atomicMax(&g_mm[1], M);
        }
    } else {
        // Border min/max: 4 rows x GX blocks x 256 threads = 19456 >= 18879.
        const int k = ((by - HOUT) * GX + blockIdx.x) * 256 + tid;
        unsigned km = 0xFFFFFFFFu, kM = 0u;
        if (k < NBORDER) {
            int row, col;
            if (k < 31 * WW) {                // full border rows: 0..14, 304..319
                const int r = k / WW;
                row = (r < PADK) ? r : r + HOUT;
                col = k % WW;
            } else {                          // side cols of interior rows
                const int k2 = k - 31 * WW;
                row = PADK + k2 / 31;
                const int c = k2 % 31;
                col = (c < PADK) ? c : c + HOUT;
            }
            const float v = fp[row * WW + col];
            km = kM = encf(v);
        }
        km = __reduce_min_sync(0xFFFFFFFFu, km);
        kM = __reduce_max_sync(0xFFFFFFFFu, kM);
        if (lane == 0) { swmin[w] = km; swmax[w] = kM; }
        __syncthreads();
#if __CUDA_ARCH__ >= 900
        cudaGridDependencySynchronize();   // g_mm init lives in k_fill
#endif
        if (tid == 0) {
            unsigned m = 0xFFFFFFFFu, M = 0u;
            #pragma unroll
            for (int i = 0; i < NWARP; ++i) { m = min(m, swmin[i]); M = max(M, swmax[i]); }
            atomicMin(&g_mm[0], m);
            atomicMax(&g_mm[1], M);
        }
    }
}

// Vectorized threshold. PDL: fp loads (input) before the dependency sync.
__global__ __launch_bounds__(256) void k_thresh(
    const float* __restrict__ fp, float* __restrict__ out)
{
    const int idx4 = blockIdx.x * 256 + threadIdx.x;
    if (idx4 >= (HH * WW) / 4) return;
    const int base = idx4 * 4;
    const int i = base / WW;
    const int j0 = base % WW;
    const bool rowin = (i >= PADK) && (i < PADK + HOUT);

    float4 fv = ((const float4*)fp)[idx4];     // input read — overlaps conv tail

#if __CUDA_ARCH__ >= 900
    cudaGridDependencySynchronize();           // wait for conv's out + g_mm
#endif
    const float mn  = decf(g_mm[0]);
    const float mxv = decf(g_mm[1]) - mn;      // max of (out - min)
    const float s   = (mxv != 0.0f) ? (100.0f / mxv) : 1.0f;

    float4 ov = ((const float4*)out)[idx4];
    float r[4] = {ov.x, ov.y, ov.z, ov.w};
    float f[4] = {fv.x, fv.y, fv.z, fv.w};
    #pragma unroll
    for (int c = 0; c < 4; ++c) {
        const int j = j0 + c;
        const bool inter = rowin && (j >= PADK) && (j < PADK + HOUT);
        const float src = inter ? r[c] : f[c];
        const float t = (src - mn) * s;
        r[c] = (t > 55.0f) ? 100.0f : 0.0f;
    }
    ((float4*)out)[idx4] = make_float4(r[0], r[1], r[2], r[3]);
}

extern "C" void kernel_launch(void* const* d_in, const int* in_sizes, int n_in,
                              void* d_out, int out_size)
{
    const float* fp   = (const float*)d_in[0];   // fprint
    const int*   fmap = (const int*)d_in[1];     // freq_map
    const int*   tmap = (const int*)d_in[2];     // theta_map
    float* out = (float*)d_out;

    dim3 fgrid(180, 2, 2);
    k_fill<<<fgrid, 128>>>();

    cudaLaunchAttribute pdl[1];
    pdl[0].id = cudaLaunchAttributeProgrammaticStreamSerialization;
    pdl[0].val.programmaticStreamSerializationAllowed = 1;

    {
        cudaLaunchConfig_t cfg = {};
        cfg.gridDim = dim3(GX, HOUT + 4);        // 19 x 293
        cfg.blockDim = dim3(256);
        cfg.dynamicSmemBytes = 0;
        cfg.stream = 0;
        cfg.attrs = pdl;
        cfg.numAttrs = 1;
        cudaLaunchKernelEx(&cfg, k_conv, fp, fmap, tmap, out);
    }
    {
        cudaLaunchConfig_t cfg = {};
        cfg.gridDim = dim3((HH * WW / 4 + 255) / 256);
        cfg.blockDim = dim3(256);
        cfg.dynamicSmemBytes = 0;
        cfg.stream = 0;
        cfg.attrs = pdl;
        cfg.numAttrs = 1;
        cudaLaunchKernelEx(&cfg, k_thresh, fp, out);
    }
}

// round 16
// speedup vs baseline: 1.5886x; 1.1414x over previous
#include <cuda_runtime.h>
#include <cuda_bf16.h>

#define HH 320
#define WW 320
#define KS 31
#define PADK 15
#define HOUT 289        // 320 - 16 - 15
#define NCOMBO 3600     // 180 thetas x 20 freqs
#define KROW 32         // padded kernel row (31 + 1 zero)
#define KSTRIDE (KS * KROW)   // 992 floats per combo = 31 x 128B lines

#define PXB 16          // pixel columns per block (two per warp)
#define NWARP 8
#define SMR2 32         // smem rows: 31 + 1 (covers two output rows)
#define SMC 48          // smem cols (46 used, padded)
#define GX 19           // ceil(289/16)
#define GYC 145         // ceil(289/2) conv block-rows (2 output rows each)
#define NBORDER 18879   // 320^2 - 289^2

// Precomputed Gabor kernel table: [3600][31*32] floats = 14.27 MB (L2-resident).
__device__ __align__(16) float g_ker[NCOMBO * KSTRIDE];
// Scratch for global min/max (monotonic-uint encoded floats).
__device__ unsigned g_mm[2];

__device__ __forceinline__ unsigned encf(float f) {
    unsigned u = __float_as_uint(f);
    return (u & 0x80000000u) ? ~u : (u | 0x80000000u);
}
__device__ __forceinline__ float decf(unsigned u) {
    return (u & 0x80000000u) ? __uint_as_float(u ^ 0x80000000u)
                             : __uint_as_float(~u);
}

// Fill the kernel table (validated Chebyshev form, unchanged from R11/R15).
// grid = (180, 2, 2), block = 128.
__global__ __launch_bounds__(128) void k_fill()
{
    __shared__ float s_st, s_ct;
    if (threadIdx.x == 0) {
        if (blockIdx.x == 0 && blockIdx.y == 0 && blockIdx.z == 0) {
            g_mm[0] = 0xFFFFFFFFu;  // min identity (encoded)
            g_mm[1] = 0u;           // max identity
        }
        const float th = (float)blockIdx.x / 180.0f * 3.14159265358979323846f;
        float st, ct;
        sincosf(th, &st, &ct);      // precise — same values as validated kernel
        s_st = st; s_ct = ct;
    }
    __syncthreads();

    const int t    = blockIdx.x;
    const int qi   = threadIdx.x;
    const int row  = blockIdx.y * 16 + (qi >> 3);   // 8 quads per row
    const int f0i  = blockIdx.z * 10;

    if (row < KS) {
        const float st = s_st, ct = s_ct;
        const int qcol = (qi & 7) * 4;
        const float y = (float)(row - PADK);
        const float yst = y * st;
        const float yct = y * ct;

        float env[4], c0[4], c1[4], k2[4];
        #pragma unroll
        for (int j = 0; j < 4; ++j) {
            const int b = qcol + j;                  // col 0..31 (31 = pad)
            const float x  = (float)(b - PADK);
            const float xt = fmaf(x, ct, yst);
            const float yt = fmaf(-x, st, yct);
            const float ga = fmaf(0.04f, fabsf(yt), 1.0f);
            const float gy = ga * yt;
            const float q  = fmaf(gy, gy, xt * xt);
            env[j] = (b < KS) ? __expf(q * (-1.0f / 72.0f)) : 0.0f;
            const float C  = xt * fmaf(yt, 1.0f / 45.0f, 1.0f);  // xt*(1+yt/45)
            const float d  = (6.283185307179586f * 0.0015f) * C;
            const float a0 = fmaf((float)f0i, d, (6.283185307179586f * 0.025f) * C);
            c1[j] = __cosf(a0);          // T(0)  at fi = f0i
            c0[j] = __cosf(a0 - d);      // T(-1)
            k2[j] = 2.0f * __cosf(d);
        }

        float* dst = &g_ker[(t * 20 + f0i) * KSTRIDE + row * KROW + qcol];
        #pragma unroll
        for (int fi = 0; fi < 10; ++fi) {
            float4 wv;
            wv.x = env[0] * c1[0];
            wv.y = env[1] * c1[1];
            wv.z = env[2] * c1[2];
            wv.w = env[3] * c1[3];
            *reinterpret_cast<float4*>(dst + fi * KSTRIDE) = wv;
            #pragma unroll
            for (int j = 0; j < 4; ++j) {
                const float tn = fmaf(k2[j], c1[j], -c0[j]);
                c0[j] = c1[j]; c1[j] = tn;
            }
        }
    }
#if __CUDA_ARCH__ >= 900
    cudaTriggerProgrammaticLaunchCompletion();
#endif
}

// Convolution + border min/max. gridDim = (GX, GYC + 4), block = 256.
// Conv blocks process TWO output rows (oy0, oy0+1) sharing one 32x48 patch:
// patch traffic per pixel halves (372B -> 192B). Per warp: 4 pixels / 4 accs
// (2 cols x 2 rows) -> 4 independent LDG streams. Per-pixel FP accumulation
// order identical to validated kernel.
__global__ __launch_bounds__(256) void k_conv(
    const float* __restrict__ fp,
    const int*   __restrict__ fmap,
    const int*   __restrict__ tmap,
    float* __restrict__ out)
{
    __shared__ float sm[SMR2 * SMC];
    __shared__ unsigned swmin[NWARP], swmax[NWARP];

    const int tid  = threadIdx.x;
    const int lane = tid & 31;
    const int w    = tid >> 5;
    const int by   = blockIdx.y;

    if (by < GYC) {
        const int oy0 = 2 * by;
        const int ox0 = blockIdx.x * PXB;
        const bool vr1 = (oy0 + 1 < HOUT);          // second row valid? (289 odd)

        // Pixel columns for this warp.
        const int p0 = 2 * w, p1 = 2 * w + 1;
        const int ox0p = ox0 + p0, ox1p = ox0 + p1;
        const bool vx0 = (ox0p < HOUT), vx1 = (ox1p < HOUT);
        const bool vA0 = vx0,        vA1 = vx1;          // row oy0
        const bool vB0 = vx0 && vr1, vB1 = vx1 && vr1;   // row oy0+1

        const int ciA0 = (oy0     + PADK) * WW + (ox0p + PADK);
        const int ciA1 = (oy0     + PADK) * WW + (ox1p + PADK);
        const int ciB0 = (oy0 + 1 + PADK) * WW + (ox0p + PADK);
        const int ciB1 = (oy0 + 1 + PADK) * WW + (ox1p + PADK);
        const int SAFE = PADK * WW + PADK;
        const int sA0 = vA0 ? ciA0 : SAFE;
        const int sA1 = vA1 ? ciA1 : SAFE;
        const int sB0 = vB0 ? ciB0 : SAFE;
        const int sB1 = vB1 ? ciB1 : SAFE;
        const int cbA0 = tmap[sA0] * 20 + fmap[sA0];
        const int cbA1 = tmap[sA1] * 20 + fmap[sA1];
        const int cbB0 = tmap[sB0] * 20 + fmap[sB0];
        const int cbB1 = tmap[sB1] * 20 + fmap[sB1];

        // Load patch rows oy0..oy0+31, cols ox0..ox0+47 (zero-fill OOB cols).
        // oy0+31 <= 319 always (oy0 <= 288).
        for (int i = tid; i < SMR2 * SMC; i += 256) {
            const int r = i / SMC, c = i % SMC;
            const int gx = ox0 + c;
            sm[i] = (gx < WW) ? fp[(oy0 + r) * WW + gx] : 0.0f;
        }
        __syncthreads();

#if __CUDA_ARCH__ >= 900
        cudaGridDependencySynchronize();   // wait for k_fill's g_ker/g_mm
#endif
        const float* __restrict__ krA0 = &g_ker[cbA0 * KSTRIDE];
        const float* __restrict__ krA1 = &g_ker[cbA1 * KSTRIDE];
        const float* __restrict__ krB0 = &g_ker[cbB0 * KSTRIDE];
        const float* __restrict__ krB1 = &g_ker[cbB1 * KSTRIDE];

        float aA0 = 0.0f, aA1 = 0.0f, aB0 = 0.0f, aB1 = 0.0f;
        const float* __restrict__ pr0 = &sm[p0 + lane];
        #pragma unroll
        for (int a = 0; a < KS; ++a) {
            const float wA0 = krA0[a * KROW + lane];   // 4 coalesced 128B lines
            const float wA1 = krA1[a * KROW + lane];
            const float wB0 = krB0[a * KROW + lane];
            const float wB1 = krB1[a * KROW + lane];
            const float pA0 = pr0[a * SMC];            // row-oy0 patch
            const float pA1 = pr0[a * SMC + 1];
            const float pB0 = pr0[(a + 1) * SMC];      // row-oy0+1 patch
            const float pB1 = pr0[(a + 1) * SMC + 1];
            aA0 = fmaf(pA0, wA0, aA0);
            aA1 = fmaf(pA1, wA1, aA1);
            aB0 = fmaf(pB0, wB0, aB0);
            aB1 = fmaf(pB1, wB1, aB1);
        }
        #pragma unroll
        for (int off = 16; off > 0; off >>= 1) {
            aA0 += __shfl_down_sync(0xFFFFFFFFu, aA0, off);
            aA1 += __shfl_down_sync(0xFFFFFFFFu, aA1, off);
            aB0 += __shfl_down_sync(0xFFFFFFFFu, aB0, off);
            aB1 += __shfl_down_sync(0xFFFFFFFFu, aB1, off);
        }

        if (lane == 0) {
            if (vA0) out[ciA0] = aA0;
            if (vA1) out[ciA1] = aA1;
            if (vB0) out[ciB0] = aB0;
            if (vB1) out[ciB1] = aB1;
            unsigned m = 0xFFFFFFFFu, M = 0u;
            if (vA0) { const unsigned e = encf(aA0); m = min(m, e); M = max(M, e); }
            if (vA1) { const unsigned e = encf(aA1); m = min(m, e); M = max(M, e); }
            if (vB0) { const unsigned e = encf(aB0); m = min(m, e); M = max(M, e); }
            if (vB1) { const unsigned e = encf(aB1); m = min(m, e); M = max(M, e); }
            swmin[w] = m;
            swmax[w] = M;
        }
        __syncthreads();
        if (tid == 0) {
            unsigned m = 0xFFFFFFFFu, M = 0u;
            #pragma unroll
            for (int i = 0; i < NWARP; ++i) { m = min(m, swmin[i]); M = max(M, swmax[i]); }
            atomicMin(&g_mm[0], m);
            atomicMax(&g_mm[1], M);
        }
    } else {
        // Border min/max: 4 rows x GX blocks x 256 threads = 19456 >= 18879.
        const int k = ((by - GYC) * GX + blockIdx.x) * 256 + tid;
        unsigned km = 0xFFFFFFFFu, kM = 0u;
        if (k < NBORDER) {
            int row, col;
            if (k < 31 * WW) {                // full border rows: 0..14, 304..319
                const int r = k / WW;
                row = (r < PADK) ? r : r + HOUT;
                col = k % WW;
            } else {                          // side cols of interior rows
                const int k2 = k - 31 * WW;
                row = PADK + k2 / 31;
                const int c = k2 % 31;
                col = (c < PADK) ? c : c + HOUT;
            }
            const float v = fp[row * WW + col];
            km = kM = encf(v);
        }
        km = __reduce_min_sync(0xFFFFFFFFu, km);
        kM = __reduce_max_sync(0xFFFFFFFFu, kM);
        if (lane == 0) { swmin[w] = km; swmax[w] = kM; }
        __syncthreads();
#if __CUDA_ARCH__ >= 900
        cudaGridDependencySynchronize();   // g_mm init lives in k_fill
#endif
        if (tid == 0) {
            unsigned m = 0xFFFFFFFFu, M = 0u;
            #pragma unroll
            for (int i = 0; i < NWARP; ++i) { m = min(m, swmin[i]); M = max(M, swmax[i]); }
            atomicMin(&g_mm[0], m);
            atomicMax(&g_mm[1], M);
        }
    }
}

// Vectorized threshold. PDL: fp loads (input) before the dependency sync.
__global__ __launch_bounds__(256) void k_thresh(
    const float* __restrict__ fp, float* __restrict__ out)
{
    const int idx4 = blockIdx.x * 256 + threadIdx.x;
    if (idx4 >= (HH * WW) / 4) return;
    const int base = idx4 * 4;
    const int i = base / WW;
    const int j0 = base % WW;
    const bool rowin = (i >= PADK) && (i < PADK + HOUT);

    float4 fv = ((const float4*)fp)[idx4];     // input read — overlaps conv tail

#if __CUDA_ARCH__ >= 900
    cudaGridDependencySynchronize();           // wait for conv's out + g_mm
#endif
    const float mn  = decf(g_mm[0]);
    const float mxv = decf(g_mm[1]) - mn;      // max of (out - min)
    const float s   = (mxv != 0.0f) ? (100.0f / mxv) : 1.0f;

    float4 ov = ((const float4*)out)[idx4];
    float r[4] = {ov.x, ov.y, ov.z, ov.w};
    float f[4] = {fv.x, fv.y, fv.z, fv.w};
    #pragma unroll
    for (int c = 0; c < 4; ++c) {
        const int j = j0 + c;
        const bool inter = rowin && (j >= PADK) && (j < PADK + HOUT);
        const float src = inter ? r[c] : f[c];
        const float t = (src - mn) * s;
        r[c] = (t > 55.0f) ? 100.0f : 0.0f;
    }
    ((float4*)out)[idx4] = make_float4(r[0], r[1], r[2], r[3]);
}

extern "C" void kernel_launch(void* const* d_in, const int* in_sizes, int n_in,
                              void* d_out, int out_size)
{
    const float* fp   = (const float*)d_in[0];   // fprint
    const int*   fmap = (const int*)d_in[1];     // freq_map
    const int*   tmap = (const int*)d_in[2];     // theta_map
    float* out = (float*)d_out;

    dim3 fgrid(180, 2, 2);
    k_fill<<<fgrid, 128>>>();

    cudaLaunchAttribute pdl[1];
    pdl[0].id = cudaLaunchAttributeProgrammaticStreamSerialization;
    pdl[0].val.programmaticStreamSerializationAllowed = 1;

    {
        cudaLaunchConfig_t cfg = {};
        cfg.gridDim = dim3(GX, GYC + 4);         // 19 x 149
        cfg.blockDim = dim3(256);
        cfg.dynamicSmemBytes = 0;
        cfg.stream = 0;
        cfg.attrs = pdl;
        cfg.numAttrs = 1;
        cudaLaunchKernelEx(&cfg, k_conv, fp, fmap, tmap, out);
    }
    {
        cudaLaunchConfig_t cfg = {};
        cfg.gridDim = dim3((HH * WW / 4 + 255) / 256);
        cfg.blockDim = dim3(256);
        cfg.dynamicSmemBytes = 0;
        cfg.stream = 0;
        cfg.attrs = pdl;
        cfg.numAttrs = 1;
        cudaLaunchKernelEx(&cfg, k_thresh, fp, out);
    }
}